// round 4
// baseline (speedup 1.0000x reference)
#include <cuda_runtime.h>

#define B_    16
#define C_    64
#define WH    65536                 // 256*256
#define NELEM (B_ * C_ * WH)        // 67,108,864 elements
#define EPS_  0.001f

#define NBLK        888             // 148 SMs x 6 CTAs, all co-resident
#define NCHUNK_ST   4096            // stats chunks: (plane)*4 + sub, 16384 floats
#define NCHUNK_NM   16384           // norm chunks: 1024 float4 each

// ---- scratch (device globals) ----
__device__ float        g_Sp[NCHUNK_ST];     // per-stats-chunk partial sum
__device__ float        g_Qp[NCHUNK_ST];     // per-stats-chunk partial sumsq
__device__ int          g_cntc[B_ * 4];      // per (batch, sub) masked count
__device__ float        g_inv[C_];           // 1/sqrt(var+eps)
__device__ volatile int g_flag;              // release flag (reset each launch)
__device__ int          g_arrive, g_depart;  // barrier counters (self-resetting)

__global__ void __launch_bounds__(256, 6) k_fused(const float* __restrict__ x,
                                                  float* __restrict__ out) {
    const int tid = threadIdx.x;
    __shared__ float sh_x00[B_ * C_];
    __shared__ int   sh_n[B_];
    __shared__ int   sh_nmax;
    __shared__ int   sh_last;
    __shared__ float ss[8], sq[8];

    // ================= phase 1: stats (zeros outside mask => no mask needed)
    for (int sblk = blockIdx.x; sblk < NCHUNK_ST; sblk += NBLK) {
        int plane = sblk >> 2;
        int sub   = sblk & 3;
        const float4* base  = (const float4*)(x + (size_t)plane * WH + sub * 16384);
        const float4* base1 = (const float4*)(x + (size_t)(plane + 1) * WH + sub * 16384);
        bool docnt = ((plane & (C_ - 1)) == 0);

        float s0 = 0.0f, s1 = 0.0f, q0 = 0.0f, q1 = 0.0f;
        int cnt = 0;
        #pragma unroll
        for (int k = 0; k < 16; k++) {
            int i4 = k * 256 + tid;
            float4 v = __ldg(base + i4);
            s0 += v.x; q0 = fmaf(v.x, v.x, q0);
            s1 += v.y; q1 = fmaf(v.y, v.y, q1);
            s0 += v.z; q0 = fmaf(v.z, v.z, q0);
            s1 += v.w; q1 = fmaf(v.w, v.w, q1);
            if (docnt) {                         // only 64 / 4096 chunks
                float4 w = __ldg(base1 + i4);
                cnt += (int)((v.x != 0.0f) | (w.x != 0.0f))
                     + (int)((v.y != 0.0f) | (w.y != 0.0f))
                     + (int)((v.z != 0.0f) | (w.z != 0.0f))
                     + (int)((v.w != 0.0f) | (w.w != 0.0f));
            }
        }
        float s = s0 + s1, q = q0 + q1;
        #pragma unroll
        for (int o = 16; o; o >>= 1) {
            s += __shfl_xor_sync(0xFFFFFFFFu, s, o);
            q += __shfl_xor_sync(0xFFFFFFFFu, q, o);
        }
        int w = tid >> 5;
        if (docnt) cnt = __reduce_add_sync(0xFFFFFFFFu, cnt);
        if ((tid & 31) == 0) { ss[w] = s; sq[w] = q; }
        __syncthreads();
        if (tid == 0) {
            float S = 0.0f, Q = 0.0f;
            #pragma unroll
            for (int i = 0; i < 8; i++) { S += ss[i]; Q += sq[i]; }
            g_Sp[sblk] = S;                      // plain stores, no atomics
            g_Qp[sblk] = Q;
        }
        if (docnt && (tid & 31) == 0 && w == 0)
            ;                                    // cnt currently in warp 0..7 lanes
        if (docnt) {
            __shared__ int scn[8];
            if ((tid & 31) == 0) scn[w] = cnt;
            __syncthreads();
            if (tid == 0) {
                int t = 0;
                #pragma unroll
                for (int i = 0; i < 8; i++) t += scn[i];
                g_cntc[(plane >> 6) * 4 + sub] = t;
            }
        }
        __syncthreads();
    }

    // ================= grid barrier; last arriver finalizes inline
    __syncthreads();
    if (tid == 0) {
        __threadfence();
        int old = atomicAdd(&g_arrive, 1);
        sh_last = (old == NBLK - 1) ? 1 : 0;
    }
    __syncthreads();

    if (sh_last) {
        // ---- finalize with this block's 256 threads (everything L2-hot) ----
        int c = tid >> 2, j = tid & 3;           // 4 threads per channel
        #pragma unroll
        for (int r = 0; r < 4; r++)              // x00 for all 1024 planes
            sh_x00[tid + r * 256] = __ldg(&x[(size_t)(tid + r * 256) << 16]);
        int cnt = (tid < B_ * 4) ? g_cntc[tid] : 0;
        float S = 0.0f, Q = 0.0f;
        #pragma unroll
        for (int b4 = 0; b4 < 4; b4++) {         // this thread: batches j*4..j*4+3
            int b = j * 4 + b4;
            int pbase = ((b * C_ + c) << 2);
            #pragma unroll
            for (int ch = 0; ch < 4; ch++) {
                S += g_Sp[pbase + ch];
                Q += g_Qp[pbase + ch];
            }
        }
        if (tid < B_ * 4) {                      // counts: 4 subs per batch
            cnt += __shfl_xor_sync(0xFFFFFFFFu, cnt, 1, 4);
            cnt += __shfl_xor_sync(0xFFFFFFFFu, cnt, 2, 4);
            if ((tid & 3) == 0) sh_n[tid >> 2] = cnt;
        }
        __syncthreads();
        if (tid == 0) {
            int nmax = 0;
            #pragma unroll
            for (int b = 0; b < B_; b++) nmax = max(nmax, sh_n[b]);
            sh_nmax = nmax;
        }
        __syncthreads();
        int nmax = sh_nmax;
        #pragma unroll
        for (int b4 = 0; b4 < 4; b4++) {         // pad terms for batches j*4..j*4+3
            int b = j * 4 + b4;
            float pad = (float)(nmax - sh_n[b]);
            float x0  = sh_x00[b * C_ + c];
            S = fmaf(pad, x0, S);
            Q = fmaf(pad * x0, x0, Q);
        }
        S += __shfl_xor_sync(0xFFFFFFFFu, S, 1, 4);
        S += __shfl_xor_sync(0xFFFFFFFFu, S, 2, 4);
        Q += __shfl_xor_sync(0xFFFFFFFFu, Q, 1, 4);
        Q += __shfl_xor_sync(0xFFFFFFFFu, Q, 2, 4);
        if (j == 0) {
            float total = (float)(B_ * nmax);
            float mean  = S / total;
            float var   = Q / total - mean * mean;
            g_inv[c] = rsqrtf(var + EPS_);
        }
        __syncthreads();
        if (tid == 0) { __threadfence(); g_flag = 1; }
    } else {
        if (tid == 0) { while (g_flag == 0) __nanosleep(128); }
        __syncthreads();
        __threadfence();                         // acquire: order g_inv reads
    }

    // ================= phase 2: out = x * inv[c], branch-free
    for (int nblk = blockIdx.x; nblk < NCHUNK_NM; nblk += NBLK) {
        size_t base4 = (size_t)nblk * 1024;
        int c = (int)(base4 >> 14) & (C_ - 1);
        float inv = __ldg(&g_inv[c]);
        float4 v0 = __ldcs((const float4*)x + base4 +   0 + tid);
        float4 v1 = __ldcs((const float4*)x + base4 + 256 + tid);
        float4 v2 = __ldcs((const float4*)x + base4 + 512 + tid);
        float4 v3 = __ldcs((const float4*)x + base4 + 768 + tid);
        float4 o;
        o.x = v0.x * inv; o.y = v0.y * inv; o.z = v0.z * inv; o.w = v0.w * inv;
        __stcs((float4*)out + base4 +   0 + tid, o);
        o.x = v1.x * inv; o.y = v1.y * inv; o.z = v1.z * inv; o.w = v1.w * inv;
        __stcs((float4*)out + base4 + 256 + tid, o);
        o.x = v2.x * inv; o.y = v2.y * inv; o.z = v2.z * inv; o.w = v2.w * inv;
        __stcs((float4*)out + base4 + 512 + tid, o);
        o.x = v3.x * inv; o.y = v3.y * inv; o.z = v3.z * inv; o.w = v3.w * inv;
        __stcs((float4*)out + base4 + 768 + tid, o);
    }

    // ================= reset sync state for the next graph replay
    __syncthreads();
    if (tid == 0) {
        int old = atomicAdd(&g_depart, 1);
        if (old == NBLK - 1) { g_flag = 0; g_arrive = 0; g_depart = 0; }
    }
}

extern "C" void kernel_launch(void* const* d_in, const int* in_sizes, int n_in,
                              void* d_out, int out_size) {
    const float* x = (const float*)d_in[0];
    float* out = (float*)d_out;
    k_fused<<<NBLK, 256>>>(x, out);
}

// round 5
// speedup vs baseline: 1.0213x; 1.0213x over previous
#include <cuda_runtime.h>

#define B_    16
#define C_    64
#define WH    65536                 // 256*256
#define NELEM (B_ * C_ * WH)        // 67,108,864 elements
#define EPS_  0.001f

#define NBLK_ST     1036            // 148 SMs x 7 — persistent stats grid
#define NCHUNK_ST   4096            // stats chunks: plane*4 + sub, 16384 floats
#define NBLK_NORM   16384           // 1024 float4 per block

// ---- scratch (device globals; plain stores, rewritten every launch) ----
__device__ float g_Sp[NCHUNK_ST];            // partial sum  [(b*64+c)*4 + sub]
__device__ float g_Qp[NCHUNK_ST];            // partial sumsq
__device__ int   g_cntc[B_ * 4];             // masked count [(b)*4 + sub]

// ---- stats: S_c = sum x, Q_c = sum x^2 over everything (unmasked pixels are
// exactly 0 in all channels, so the mask is only needed for COUNTS, which the
// channel-0 chunks compute by also peeking at channel 1). ----
__global__ void __launch_bounds__(256) k_stats(const float* __restrict__ x) {
    const int tid = threadIdx.x;
    __shared__ float ss[8], sq[8];
    __shared__ int   scn[8];
    for (int sblk = blockIdx.x; sblk < NCHUNK_ST; sblk += NBLK_ST) {
        int plane = sblk >> 2;
        int sub   = sblk & 3;
        const float4* base  = (const float4*)(x + (size_t)plane * WH + sub * 16384);
        const float4* base1 = (const float4*)(x + (size_t)(plane + 1) * WH + sub * 16384);
        bool docnt = ((plane & (C_ - 1)) == 0);

        float s0 = 0.0f, s1 = 0.0f, q0 = 0.0f, q1 = 0.0f;
        int cnt = 0;
        #pragma unroll
        for (int k = 0; k < 16; k++) {
            int i4 = k * 256 + tid;
            float4 v = __ldg(base + i4);
            s0 += v.x; q0 = fmaf(v.x, v.x, q0);
            s1 += v.y; q1 = fmaf(v.y, v.y, q1);
            s0 += v.z; q0 = fmaf(v.z, v.z, q0);
            s1 += v.w; q1 = fmaf(v.w, v.w, q1);
            if (docnt) {                         // only 64 / 4096 chunks
                float4 w = __ldg(base1 + i4);
                cnt += (int)((v.x != 0.0f) | (w.x != 0.0f))
                     + (int)((v.y != 0.0f) | (w.y != 0.0f))
                     + (int)((v.z != 0.0f) | (w.z != 0.0f))
                     + (int)((v.w != 0.0f) | (w.w != 0.0f));
            }
        }
        float s = s0 + s1, q = q0 + q1;
        #pragma unroll
        for (int o = 16; o; o >>= 1) {
            s += __shfl_xor_sync(0xFFFFFFFFu, s, o);
            q += __shfl_xor_sync(0xFFFFFFFFu, q, o);
        }
        int w = tid >> 5;
        if (docnt) cnt = __reduce_add_sync(0xFFFFFFFFu, cnt);
        if ((tid & 31) == 0) { ss[w] = s; sq[w] = q; scn[w] = cnt; }
        __syncthreads();
        if (tid == 0) {
            float S = 0.0f, Q = 0.0f;
            #pragma unroll
            for (int i = 0; i < 8; i++) { S += ss[i]; Q += sq[i]; }
            g_Sp[sblk] = S;
            g_Qp[sblk] = Q;
            if (docnt) {
                int t = 0;
                #pragma unroll
                for (int i = 0; i < 8; i++) t += scn[i];
                g_cntc[(plane >> 6) * 4 + sub] = t;
            }
        }
        __syncthreads();
    }
}

// ---- normalize: out = x * inv[c] unconditionally. Warp 0 of every block
// recomputes inv for its channel from the L2-hot partials (deterministic:
// identical data + order in every block) while the x loads are in flight. ----
__global__ void __launch_bounds__(256) k_norm(const float* __restrict__ x,
                                              float* __restrict__ out) {
    const int tid = threadIdx.x;
    int blk = (NBLK_NORM - 1) - blockIdx.x;          // reverse: catch L2 tail
    size_t base4 = (size_t)blk * 1024;               // float4 index of block base
    int c = (int)(base4 >> 14) & (C_ - 1);           // block lies in one plane
    __shared__ float sh_inv;

    // front-batch the streaming loads (independent of inv)
    float4 v0 = __ldcs((const float4*)x + base4 +   0 + tid);
    float4 v1 = __ldcs((const float4*)x + base4 + 256 + tid);
    float4 v2 = __ldcs((const float4*)x + base4 + 512 + tid);
    float4 v3 = __ldcs((const float4*)x + base4 + 768 + tid);

    if (tid < 32) {                                  // inline finalize, warp 0
        int b = tid & 15;                            // lanes 16-31 mirror 0-15
        int pbase = (b * C_ + c) << 2;
        float4 s4 = *(const float4*)&g_Sp[pbase];    // L2-hot after first blocks
        float4 q4 = *(const float4*)&g_Qp[pbase];
        int4  c4  = *(const int4*)&g_cntc[b << 2];
        float x00 = __ldg(&x[(size_t)(b * C_ + c) << 16]);
        int   n   = (c4.x + c4.y) + (c4.z + c4.w);
        float S   = (s4.x + s4.y) + (s4.z + s4.w);
        float Q   = (q4.x + q4.y) + (q4.z + q4.w);
        int nmax = n;
        #pragma unroll
        for (int o = 8; o; o >>= 1)
            nmax = max(nmax, __shfl_xor_sync(0xFFFFFFFFu, nmax, o, 16));
        float pad = (float)(nmax - n);
        S = fmaf(pad, x00, S);
        Q = fmaf(pad * x00, x00, Q);
        #pragma unroll
        for (int o = 8; o; o >>= 1) {
            S += __shfl_xor_sync(0xFFFFFFFFu, S, o, 16);
            Q += __shfl_xor_sync(0xFFFFFFFFu, Q, o, 16);
        }
        if (tid == 0) {
            float total = (float)(B_ * nmax);
            float mean  = S / total;
            float var   = Q / total - mean * mean;
            sh_inv = rsqrtf(var + EPS_);
        }
    }
    __syncthreads();
    float inv = sh_inv;

    float4 o;
    o.x = v0.x * inv; o.y = v0.y * inv; o.z = v0.z * inv; o.w = v0.w * inv;
    __stcs((float4*)out + base4 +   0 + tid, o);
    o.x = v1.x * inv; o.y = v1.y * inv; o.z = v1.z * inv; o.w = v1.w * inv;
    __stcs((float4*)out + base4 + 256 + tid, o);
    o.x = v2.x * inv; o.y = v2.y * inv; o.z = v2.z * inv; o.w = v2.w * inv;
    __stcs((float4*)out + base4 + 512 + tid, o);
    o.x = v3.x * inv; o.y = v3.y * inv; o.z = v3.z * inv; o.w = v3.w * inv;
    __stcs((float4*)out + base4 + 768 + tid, o);
}

extern "C" void kernel_launch(void* const* d_in, const int* in_sizes, int n_in,
                              void* d_out, int out_size) {
    const float* x = (const float*)d_in[0];
    float* out = (float*)d_out;
    k_stats<<<NBLK_ST, 256>>>(x);
    k_norm <<<NBLK_NORM, 256>>>(x, out);
}

// round 6
// speedup vs baseline: 1.1026x; 1.0796x over previous
#include <cuda_runtime.h>

#define B_    16
#define C_    64
#define WH    65536                 // 256*256
#define NELEM (B_ * C_ * WH)        // 67,108,864 elements
#define EPS_  0.001f

#define NBLK_ST     4096            // stats chunks: plane*4 + sub, 16384 floats
#define NBLK_NORM   16384           // 1024 float4 per block

// ---- scratch (device globals; plain stores, rewritten every launch) ----
__device__ float g_Sp[NBLK_ST];              // partial sum  [(b*64+c)*4 + sub]
__device__ float g_Qp[NBLK_ST];              // partial sumsq
__device__ int   g_cntc[B_ * 4];             // masked count [b*4 + sub]
__device__ float g_inv[C_];                  // 1/sqrt(var+eps)
__device__ int   g_done;                     // last-block-done counter (self-reset)

__device__ __forceinline__ void acc_f32x2(unsigned long long& s,
                                          unsigned long long& q,
                                          unsigned long long v) {
    asm("add.rn.f32x2 %0, %0, %1;" : "+l"(s) : "l"(v));
    asm("fma.rn.f32x2 %0, %1, %1, %0;" : "+l"(q) : "l"(v));
}
__device__ __forceinline__ float2 unpack2(unsigned long long v) {
    float2 r;
    asm("mov.b64 {%0, %1}, %2;" : "=f"(r.x), "=f"(r.y) : "l"(v));
    return r;
}

// ---- stats: S_c = sum x, Q_c = sum x^2 over everything (unmasked pixels are
// exactly 0 in every channel => mask only needed for COUNTS, computed by the
// 64 channel-0 chunks which also peek at channel 1). Packed f32x2 math keeps
// the FMA pipe under the DRAM cycle budget. Last finishing block finalizes. ----
__global__ void __launch_bounds__(256) k_stats(const float* __restrict__ x) {
    const int tid = threadIdx.x;
    const int blk = blockIdx.x;
    int plane = blk >> 2;
    int sub   = blk & 3;
    bool docnt = ((plane & (C_ - 1)) == 0);
    __shared__ float ss[8], sq[8];
    __shared__ int   scn[8];
    __shared__ int   sh_last;
    __shared__ int   sh_n[B_];
    __shared__ int   sh_nmax;

    float s, q;
    int cnt = 0;
    if (!docnt) {
        const ulonglong2* base =
            (const ulonglong2*)(x + (size_t)plane * WH + sub * 16384);
        unsigned long long sA = 0, sB = 0, qA = 0, qB = 0;
        #pragma unroll
        for (int k = 0; k < 16; k++) {
            ulonglong2 v = __ldg(base + k * 256 + tid);
            acc_f32x2(sA, qA, v.x);
            acc_f32x2(sB, qB, v.y);
        }
        float2 a = unpack2(sA), b2 = unpack2(sB);
        float2 c2 = unpack2(qA), d2 = unpack2(qB);
        s = (a.x + a.y) + (b2.x + b2.y);
        q = (c2.x + c2.y) + (d2.x + d2.y);
    } else {                                     // 64 / 4096 chunks: also count
        const float4* base  = (const float4*)(x + (size_t)plane * WH + sub * 16384);
        const float4* base1 = (const float4*)(x + (size_t)(plane + 1) * WH + sub * 16384);
        float s0 = 0.0f, s1 = 0.0f, q0 = 0.0f, q1 = 0.0f;
        #pragma unroll
        for (int k = 0; k < 16; k++) {
            int i4 = k * 256 + tid;
            float4 v = __ldg(base + i4);
            float4 w = __ldg(base1 + i4);
            s0 += v.x; q0 = fmaf(v.x, v.x, q0);
            s1 += v.y; q1 = fmaf(v.y, v.y, q1);
            s0 += v.z; q0 = fmaf(v.z, v.z, q0);
            s1 += v.w; q1 = fmaf(v.w, v.w, q1);
            cnt += (int)((v.x != 0.0f) | (w.x != 0.0f))
                 + (int)((v.y != 0.0f) | (w.y != 0.0f))
                 + (int)((v.z != 0.0f) | (w.z != 0.0f))
                 + (int)((v.w != 0.0f) | (w.w != 0.0f));
        }
        s = s0 + s1; q = q0 + q1;
        cnt = __reduce_add_sync(0xFFFFFFFFu, cnt);
    }
    #pragma unroll
    for (int o = 16; o; o >>= 1) {
        s += __shfl_xor_sync(0xFFFFFFFFu, s, o);
        q += __shfl_xor_sync(0xFFFFFFFFu, q, o);
    }
    int w = tid >> 5;
    if ((tid & 31) == 0) { ss[w] = s; sq[w] = q; scn[w] = cnt; }
    __syncthreads();
    if (tid == 0) {
        float S = 0.0f, Q = 0.0f;
        #pragma unroll
        for (int i = 0; i < 8; i++) { S += ss[i]; Q += sq[i]; }
        g_Sp[blk] = S;
        g_Qp[blk] = Q;
        if (docnt) {
            int t = 0;
            #pragma unroll
            for (int i = 0; i < 8; i++) t += scn[i];
            g_cntc[(plane >> 6) * 4 + sub] = t;
        }
        __threadfence();                         // release partials
        int old = atomicAdd(&g_done, 1);
        sh_last = (old == NBLK_ST - 1) ? 1 : 0;
        if (sh_last) g_done = 0;                 // reset for next graph replay
    }
    __syncthreads();
    if (!sh_last) return;

    // ---- inline finalize, exactly one block, partials L2-hot ----
    __threadfence();                             // acquire
    if (tid < B_) {
        int4 c4 = *(const int4*)&g_cntc[tid << 2];
        sh_n[tid] = (c4.x + c4.y) + (c4.z + c4.w);
    }
    __syncthreads();
    if (tid == 0) {
        int nmax = 0;
        #pragma unroll
        for (int b = 0; b < B_; b++) nmax = max(nmax, sh_n[b]);
        sh_nmax = nmax;
    }
    __syncthreads();
    int nmax = sh_nmax;
    int c = tid >> 2, j = tid & 3;               // 4 threads per channel
    float S = 0.0f, Q = 0.0f;
    #pragma unroll
    for (int b4 = 0; b4 < 4; b4++) {             // this thread: batches j*4+b4
        int b = j * 4 + b4;
        int pbase = (b * C_ + c) << 2;
        float4 s4 = *(const float4*)&g_Sp[pbase];
        float4 q4 = *(const float4*)&g_Qp[pbase];
        float x00 = __ldg(&x[(size_t)(b * C_ + c) << 16]);
        float pad = (float)(nmax - sh_n[b]);
        S += (s4.x + s4.y) + (s4.z + s4.w);
        Q += (q4.x + q4.y) + (q4.z + q4.w);
        S = fmaf(pad, x00, S);
        Q = fmaf(pad * x00, x00, Q);
    }
    S += __shfl_xor_sync(0xFFFFFFFFu, S, 1, 4);
    S += __shfl_xor_sync(0xFFFFFFFFu, S, 2, 4);
    Q += __shfl_xor_sync(0xFFFFFFFFu, Q, 1, 4);
    Q += __shfl_xor_sync(0xFFFFFFFFu, Q, 2, 4);
    if (j == 0) {
        float total = (float)(B_ * nmax);
        float mean  = S / total;
        float var   = Q / total - mean * mean;
        g_inv[c] = rsqrtf(var + EPS_);
    }
}

// ---- normalize: out = x * inv[c] unconditionally (unmasked x are exact 0;
// (0,0) pad override is also x00*inv). Reverse order to catch the L2 tail. ----
__global__ void __launch_bounds__(256) k_norm(const float* __restrict__ x,
                                              float* __restrict__ out) {
    const int tid = threadIdx.x;
    int blk = (NBLK_NORM - 1) - blockIdx.x;
    size_t base4 = (size_t)blk * 1024;               // float4 index of block base
    int c = (int)(base4 >> 14) & (C_ - 1);           // block lies in one plane
    float inv = __ldg(&g_inv[c]);
    float4 v0 = __ldcs((const float4*)x + base4 +   0 + tid);
    float4 v1 = __ldcs((const float4*)x + base4 + 256 + tid);
    float4 v2 = __ldcs((const float4*)x + base4 + 512 + tid);
    float4 v3 = __ldcs((const float4*)x + base4 + 768 + tid);
    float4 o;
    o.x = v0.x * inv; o.y = v0.y * inv; o.z = v0.z * inv; o.w = v0.w * inv;
    __stcs((float4*)out + base4 +   0 + tid, o);
    o.x = v1.x * inv; o.y = v1.y * inv; o.z = v1.z * inv; o.w = v1.w * inv;
    __stcs((float4*)out + base4 + 256 + tid, o);
    o.x = v2.x * inv; o.y = v2.y * inv; o.z = v2.z * inv; o.w = v2.w * inv;
    __stcs((float4*)out + base4 + 512 + tid, o);
    o.x = v3.x * inv; o.y = v3.y * inv; o.z = v3.z * inv; o.w = v3.w * inv;
    __stcs((float4*)out + base4 + 768 + tid, o);
}

extern "C" void kernel_launch(void* const* d_in, const int* in_sizes, int n_in,
                              void* d_out, int out_size) {
    const float* x = (const float*)d_in[0];
    float* out = (float*)d_out;
    k_stats<<<NBLK_ST, 256>>>(x);
    k_norm <<<NBLK_NORM, 256>>>(x, out);
}